// round 16
// baseline (speedup 1.0000x reference)
#include <cuda_runtime.h>
#include <cuda_fp16.h>
#include <math.h>
#include <stdint.h>

#define B_ROWS 16384
#define NSP 26
#define ND 13
#define VOCAB 100000
#define EMB_D 16
#define F0 29
#define BN_EPS 1e-5f

#define NCTA 296              // = 148 SMs x 2 co-resident CTAs (exact fit)
#define NTILE 256             // MLP tiles (64 rows each)

// ---------------------------------------------------------------------------
// Device scratch
// ---------------------------------------------------------------------------
__device__ float g_xbuf[B_ROWS * 32];      // gathered [B][32]
__device__ float g_bnpart[NCTA][64];       // per-CTA BN partials
__device__ float g_bnsc[32];               // finalized scale (cols >= F0 zero)
__device__ float g_bnsh[32];               // finalized shift
__device__ unsigned int g_ticket;          // arrival counter (never reset)
__device__ unsigned int g_release;         // release counter (never reset)

// Fragment-ordered fp16x2-packed weights
__device__ uint32_t g_wf1[12288];          // layer1 3-term [s6][nt32][lane][2]
__device__ uint32_t g_wf2[16384];          // layer2 single [kt16][nt16][lane][2]
__device__ uint32_t g_wf3[4096];           // layer3 single [kt8][nt8][lane][2]

// ---------------------------------------------------------------------------
__device__ __forceinline__ void mma_f16(float* c, uint32_t a0, uint32_t a1,
                                        uint32_t a2, uint32_t a3,
                                        uint32_t b0, uint32_t b1) {
    asm volatile(
        "mma.sync.aligned.m16n8k16.row.col.f32.f16.f16.f32 "
        "{%0,%1,%2,%3}, {%4,%5,%6,%7}, {%8,%9}, {%0,%1,%2,%3};"
        : "+f"(c[0]), "+f"(c[1]), "+f"(c[2]), "+f"(c[3])
        : "r"(a0), "r"(a1), "r"(a2), "r"(a3), "r"(b0), "r"(b1));
}

__device__ __forceinline__ void ldsm_x4(uint32_t* r, uint32_t addr) {
    asm volatile("ldmatrix.sync.aligned.m8n8.x4.shared.b16 {%0,%1,%2,%3}, [%4];"
                 : "=r"(r[0]), "=r"(r[1]), "=r"(r[2]), "=r"(r[3]) : "r"(addr));
}

__device__ __forceinline__ uint32_t smem_u32(const void* p) {
    uint32_t a;
    asm("{ .reg .u64 t; cvta.to.shared.u64 t, %1; cvt.u32.u64 %0, t; }"
        : "=r"(a) : "l"(p));
    return a;
}

__device__ __forceinline__ uint32_t pack_h2(float a, float b) {
    __half2 h = __floats2half2_rn(a, b);
    return *(uint32_t*)&h;
}

__device__ __forceinline__ void split_pack_h(float h0, float h1,
                                             uint32_t& hi, uint32_t& lo) {
    __half a0 = __float2half_rn(h0);
    __half a1 = __float2half_rn(h1);
    __half c0 = __float2half_rn(h0 - __half2float(a0));
    __half c1 = __float2half_rn(h1 - __half2float(a1));
    hi = ((uint32_t)__half_as_ushort(a1) << 16) | __half_as_ushort(a0);
    lo = ((uint32_t)__half_as_ushort(c1) << 16) | __half_as_ushort(c0);
}

__device__ __forceinline__ unsigned short wpart_f16(float w, bool lo_part) {
    __half h = __float2half_rn(w);
    if (!lo_part) return __half_as_ushort(h);
    return __half_as_ushort(__float2half_rn(w - __half2float(h)));
}

// ---------------------------------------------------------------------------
// weight prep (fragment order), 32768 elements total
// ---------------------------------------------------------------------------
__device__ __forceinline__ void prep_one(int e, const float* __restrict__ W1,
                                         const float* __restrict__ W2,
                                         const float* __restrict__ W3) {
    if (e < 12288) {
        int r = e & 1, lane = (e >> 1) & 31, nt = (e >> 6) & 31, s = e >> 11;
        bool wlo = (s == 2 || s == 3);
        int kt = s & 1;
        int k = kt * 16 + (lane & 3) * 2 + r * 8;
        int n = nt * 8 + (lane >> 2);
        float w0 = (k < F0)     ? W1[k * 256 + n]       : 0.f;
        float w1 = (k + 1 < F0) ? W1[(k + 1) * 256 + n] : 0.f;
        g_wf1[e] = ((uint32_t)wpart_f16(w1, wlo) << 16) | wpart_f16(w0, wlo);
    } else if (e < 28672) {
        int e2 = e - 12288;
        int r = e2 & 1, lane = (e2 >> 1) & 31, nt = (e2 >> 6) & 15, kt = e2 >> 10;
        int k = kt * 16 + (lane & 3) * 2 + r * 8;
        int n = nt * 8 + (lane >> 2);
        float w0 = W2[k * 128 + n];
        float w1 = W2[(k + 1) * 128 + n];
        g_wf2[e2] = ((uint32_t)wpart_f16(w1, false) << 16) | wpart_f16(w0, false);
    } else {
        int e3 = e - 28672;
        int r = e3 & 1, lane = (e3 >> 1) & 31, nt = (e3 >> 6) & 7, kt = e3 >> 9;
        int k = kt * 16 + (lane & 3) * 2 + r * 8;
        int n = nt * 8 + (lane >> 2);
        float w0 = W3[k * 64 + n];
        float w1 = W3[(k + 1) * 64 + n];
        g_wf3[e3] = ((uint32_t)wpart_f16(w1, false) << 16) | wpart_f16(w0, false);
    }
}

// ---------------------------------------------------------------------------
// SMEM layout (64-row MLP tile). H2 aliases XHI/XLO.
// ---------------------------------------------------------------------------
#define FM_H1    0            // 64*528 = 33792 (fp16)
#define FM_XHI   33792        // 5120
#define FM_XLO   38912        // 5120 -> 44032
#define FM_H2    33792        // 64*272 = 17408 -> 51200 (alias grows past XLO)
#define FM_BIAS  51200        // b1[256] b2[128] b3[64] wf[64] bf[1]
#define FM_SC    53264
#define FM_SH    53392
#define FM_RED   53520        // 4*64 floats
#define FM_SMEM  54544

__global__ void __launch_bounds__(256, 2)
nfm_kernel(const void* __restrict__ xsparse, const float* __restrict__ xdense,
           const float* __restrict__ emb,
           const float* __restrict__ W1, const float* __restrict__ b1,
           const float* __restrict__ W2, const float* __restrict__ b2,
           const float* __restrict__ W3, const float* __restrict__ b3,
           const float* __restrict__ Wf, const float* __restrict__ bf,
           const float* __restrict__ gamma, const float* __restrict__ beta,
           float* __restrict__ out) {
    extern __shared__ char sm[];
    const uint32_t sbase = smem_u32(sm);
    float* sb1 = (float*)(sm + FM_BIAS);
    float* sb2 = sb1 + 256;
    float* sb3 = sb2 + 128;
    float* swv = sb3 + 64;
    float* sbf = swv + 64;
    float* sSC = (float*)(sm + FM_SC);
    float* sSH = (float*)(sm + FM_SH);
    float* sred = (float*)(sm + FM_RED);
    float* swarp = (float*)(sm + FM_H1);   // reuse H1 region during gather

    __shared__ int s_is64;
    __shared__ unsigned s_round;
    __shared__ int s_last;

    const int tid = threadIdx.x;
    const int cta = blockIdx.x;

    // ---- idx-width detect ----
    const int* xs_i32 = (const int*)xsparse;
    if (tid < 32) {
        unsigned m = __ballot_sync(0xffffffffu, xs_i32[2 * tid + 1] != 0);
        if (tid == 0) s_is64 = (m == 0);
    }
    __syncthreads();
    const bool is64 = (s_is64 != 0);

    // ---- balanced gather: CTA c handles rows [c*B/296, (c+1)*B/296) ----
    const long long* xs64 = (const long long*)xsparse;
    const int row_s = (int)(((long long)cta * B_ROWS) / NCTA);
    const int row_e = (int)(((long long)(cta + 1) * B_ROWS) / NCTA);
    const int nquads = (row_e - row_s) * 4;
    const int q = tid & 3;
    const int rg = row_s + (tid >> 2);
    const bool active = (tid < nquads);

    float4 cr = make_float4(0.f, 0.f, 0.f, 0.f);
    float4 dv = make_float4(0.f, 0.f, 0.f, 0.f);
    float q0 = 0.f, q1 = 0.f, q2 = 0.f, q3 = 0.f;

    if (active) {
        int idxs[NSP];
        if (is64) {
#pragma unroll
            for (int f = 0; f < NSP; f++) idxs[f] = (int)xs64[rg * NSP + f];
        } else {
#pragma unroll
            for (int f = 0; f < NSP; f++) idxs[f] = xs_i32[rg * NSP + f];
        }
        float s0 = 0.f, s1 = 0.f, s2 = 0.f, s3 = 0.f;
#pragma unroll
        for (int half = 0; half < 2; half++) {
            float4 v[13];
#pragma unroll
            for (int j = 0; j < 13; j++) {
                int f = half * 13 + j;
                v[j] = *(const float4*)(emb +
                    ((size_t)f * VOCAB + (size_t)idxs[f]) * EMB_D + q * 4);
            }
#pragma unroll
            for (int j = 0; j < 13; j++) {
                s0 += v[j].x; s1 += v[j].y; s2 += v[j].z; s3 += v[j].w;
                q0 += v[j].x * v[j].x; q1 += v[j].y * v[j].y;
                q2 += v[j].z * v[j].z; q3 += v[j].w * v[j].w;
            }
        }
        cr.x = 0.5f * (s0 * s0 - q0);
        cr.y = 0.5f * (s1 * s1 - q1);
        cr.z = 0.5f * (s2 * s2 - q2);
        cr.w = 0.5f * (s3 * s3 - q3);
        int base = q * 4;
        dv.x = (base + 0 < ND) ? xdense[rg * ND + base + 0] : 0.f;
        dv.y = (base + 1 < ND) ? xdense[rg * ND + base + 1] : 0.f;
        dv.z = (base + 2 < ND) ? xdense[rg * ND + base + 2] : 0.f;
        dv.w = (base + 3 < ND) ? xdense[rg * ND + base + 3] : 0.f;
        *(float4*)&g_xbuf[rg * 32 + q * 4] = cr;
        *(float4*)&g_xbuf[rg * 32 + 16 + q * 4] = dv;
    }

    // ---- BN partials (shuffle tree; inactive threads contribute zeros) ----
    {
        float st[16];
        st[0] = cr.x; st[1] = cr.y; st[2] = cr.z; st[3] = cr.w;
        st[4] = cr.x * cr.x; st[5] = cr.y * cr.y; st[6] = cr.z * cr.z; st[7] = cr.w * cr.w;
        st[8] = dv.x; st[9] = dv.y; st[10] = dv.z; st[11] = dv.w;
        st[12] = dv.x * dv.x; st[13] = dv.y * dv.y; st[14] = dv.z * dv.z; st[15] = dv.w * dv.w;
#pragma unroll
        for (int j = 0; j < 16; j++) {
            st[j] += __shfl_xor_sync(0xffffffffu, st[j], 4);
            st[j] += __shfl_xor_sync(0xffffffffu, st[j], 8);
            st[j] += __shfl_xor_sync(0xffffffffu, st[j], 16);
        }
        int wd = tid >> 5, lane = tid & 31;
        if (lane < 4) {
#pragma unroll
            for (int j = 0; j < 16; j++) swarp[(wd * 4 + lane) * 16 + j] = st[j];
        }
        __syncthreads();
        if (tid < 64) {
            int qq = tid >> 4, j = tid & 15;
            float acc = 0.f;
#pragma unroll
            for (int w = 0; w < 8; w++) acc += swarp[(w * 4 + qq) * 16 + j];
            int col, slot;
            if (j < 4)       { col = qq * 4 + j;          slot = col; }
            else if (j < 8)  { col = qq * 4 + (j - 4);    slot = 32 + col; }
            else if (j < 12) { col = 16 + qq * 4 + (j - 8);  slot = col; }
            else             { col = 16 + qq * 4 + (j - 12); slot = 32 + col; }
            g_bnpart[cta][slot] = acc;
        }
    }

    // ---- weight prep (CTAs 0..255 only, 128 elems each) ----
    if (cta < NTILE && tid < 128) prep_one(cta * 128 + tid, W1, W2, W3);

    // ---- biases ----
    if (tid < 256) sb1[tid] = b1[tid];
    if (tid < 128) sb2[tid] = b2[tid];
    else if (tid < 192) sb3[tid - 128] = b3[tid - 128];
    else swv[tid - 192] = Wf[tid - 192];
    if (tid == 0) sbf[0] = bf[0];

    // ---- device-wide barrier with single-CTA BN finalize ----
    __threadfence();
    __syncthreads();
    if (tid == 0) {
        unsigned t = atomicAdd(&g_ticket, 1u);
        s_round = t / (unsigned)NCTA;
        s_last = ((t % (unsigned)NCTA) == (unsigned)(NCTA - 1));
    }
    __syncthreads();
    const unsigned my_round = s_round;

    if (s_last) {
        __threadfence();   // acquire-side for partials
        int slot = tid & 63, seg = tid >> 6;    // 4 segs x 74 blocks
        float acc = 0.f;
        for (int b = seg * 74; b < seg * 74 + 74; b++)
            acc += __ldcg(&g_bnpart[b][slot]);
        sred[seg * 64 + slot] = acc;
        __syncthreads();
        if (tid < 32) {
            float s = 0.f, s2 = 0.f;
#pragma unroll
            for (int c = 0; c < 4; c++) { s += sred[c * 64 + tid]; s2 += sred[c * 64 + 32 + tid]; }
            float mean = s * (1.0f / B_ROWS);
            float var  = s2 * (1.0f / B_ROWS) - mean * mean;
            if (tid < F0) {
                float sc = gamma[tid] * rsqrtf(var + BN_EPS);
                g_bnsc[tid] = sc;
                g_bnsh[tid] = beta[tid] - mean * sc;
            } else { g_bnsc[tid] = 0.f; g_bnsh[tid] = 0.f; }
        }
        __threadfence();
        __syncthreads();
        if (tid == 0) atomicAdd(&g_release, 1u);
    } else {
        if (tid == 0) {
            unsigned v;
            do {
                asm volatile("ld.acquire.gpu.global.u32 %0, [%1];"
                             : "=r"(v) : "l"(&g_release) : "memory");
                if (v < my_round + 1u) __nanosleep(64);
            } while (v < my_round + 1u);
        }
        __syncthreads();
    }

    if (cta >= NTILE) return;   // gather-only CTAs done
    const int r0 = cta * 64;

    const int wid = tid >> 5, lane = tid & 31;
    const int lm_m   = lane >> 3;
    const int lm_row = (lane & 7) + ((lm_m & 1) << 3);
    const uint32_t lm_kadd = (uint32_t)(lm_m >> 1) * 16;
    const int mg1 = wid & 1, ng1 = wid >> 1;

    // layer-1 s=0 weight prefetch (covers scale/shift load + X staging)
    uint2 w1buf[8];
#pragma unroll
    for (int n = 0; n < 8; n++)
        w1buf[n] = __ldcg((const uint2*)&g_wf1[((ng1 * 8 + n) * 32 + lane) * 2]);

    if (tid < 32) { sSC[tid] = __ldcg(&g_bnsc[tid]); sSH[tid] = __ldcg(&g_bnsh[tid]); }
    __syncthreads();

    // ---- stage X: read gathered rows, BN + fp16 split ----
    {
        int rloc = tid >> 2, qq = tid & 3;
        float4 v0 = __ldcg((const float4*)&g_xbuf[(r0 + rloc) * 32 + qq * 8]);
        float4 v1 = __ldcg((const float4*)&g_xbuf[(r0 + rloc) * 32 + qq * 8 + 4]);
        float4 sc0 = *(const float4*)&sSC[qq * 8];
        float4 sc1 = *(const float4*)&sSC[qq * 8 + 4];
        float4 sh0 = *(const float4*)&sSH[qq * 8];
        float4 sh1 = *(const float4*)&sSH[qq * 8 + 4];
        float x0 = v0.x * sc0.x + sh0.x, x1 = v0.y * sc0.y + sh0.y;
        float x2 = v0.z * sc0.z + sh0.z, x3 = v0.w * sc0.w + sh0.w;
        float x4 = v1.x * sc1.x + sh1.x, x5 = v1.y * sc1.y + sh1.y;
        float x6 = v1.z * sc1.z + sh1.z, x7 = v1.w * sc1.w + sh1.w;
        uint4 uh, ul;
        split_pack_h(x0, x1, uh.x, ul.x);
        split_pack_h(x2, x3, uh.y, ul.y);
        split_pack_h(x4, x5, uh.z, ul.z);
        split_pack_h(x6, x7, uh.w, ul.w);
        *(uint4*)(sm + FM_XHI + rloc * 80 + qq * 16) = uh;
        *(uint4*)(sm + FM_XLO + rloc * 80 + qq * 16) = ul;
    }
    __syncthreads();

    // ================= layer 1 (3-term fp16): [64x32] x [32x256] =========
    {
        float acc[2][8][4];
#pragma unroll
        for (int m = 0; m < 2; m++)
#pragma unroll
            for (int n = 0; n < 8; n++)
#pragma unroll
                for (int j = 0; j < 4; j++) acc[m][n][j] = 0.f;

        uint32_t ro0 = (uint32_t)(mg1 * 32 + lm_row) * 80 + lm_kadd;
        uint32_t ro1 = (uint32_t)(mg1 * 32 + 16 + lm_row) * 80 + lm_kadd;

#pragma unroll
        for (int s = 0; s < 6; s++) {
            uint32_t ab = sbase + ((s >= 4) ? FM_XLO : FM_XHI) + (uint32_t)(s & 1) * 32;
            uint32_t a[2][4];
            ldsm_x4(a[0], ab + ro0);
            ldsm_x4(a[1], ab + ro1);
            uint2 wn[8];
            if (s < 5) {
#pragma unroll
                for (int n = 0; n < 8; n++)
                    wn[n] = __ldcg((const uint2*)&g_wf1[(((s + 1) * 32 + ng1 * 8 + n) * 32 + lane) * 2]);
            }
#pragma unroll
            for (int n = 0; n < 8; n++) {
                mma_f16(acc[0][n], a[0][0], a[0][1], a[0][2], a[0][3], w1buf[n].x, w1buf[n].y);
                mma_f16(acc[1][n], a[1][0], a[1][1], a[1][2], a[1][3], w1buf[n].x, w1buf[n].y);
            }
            if (s < 5) {
#pragma unroll
                for (int n = 0; n < 8; n++) w1buf[n] = wn[n];
            }
        }

#pragma unroll
        for (int mt = 0; mt < 2; mt++) {
            int rr = mg1 * 32 + mt * 16 + (lane >> 2);
#pragma unroll
            for (int n = 0; n < 8; n++) {
                int c0 = ng1 * 64 + n * 8 + (lane & 3) * 2;
                float2 bb = *(const float2*)&sb1[c0];
                float h0 = fmaxf(acc[mt][n][0] + bb.x, 0.f);
                float h1 = fmaxf(acc[mt][n][1] + bb.y, 0.f);
                *(uint32_t*)(sm + FM_H1 + rr * 528 + c0 * 2) = pack_h2(h0, h1);
                float h2 = fmaxf(acc[mt][n][2] + bb.x, 0.f);
                float h3 = fmaxf(acc[mt][n][3] + bb.y, 0.f);
                *(uint32_t*)(sm + FM_H1 + (rr + 8) * 528 + c0 * 2) = pack_h2(h2, h3);
            }
        }
    }
    __syncthreads();

    // ================= layer 2 (single fp16): [64x256] x [256x128] ========
    {
        const int mg = wid & 1, ng = wid >> 1;
        float acc[2][4][4];
#pragma unroll
        for (int m = 0; m < 2; m++)
#pragma unroll
            for (int n = 0; n < 4; n++)
#pragma unroll
                for (int j = 0; j < 4; j++) acc[m][n][j] = 0.f;

        uint32_t ro0 = (uint32_t)(mg * 32 + lm_row) * 528 + lm_kadd;
        uint32_t ro1 = (uint32_t)(mg * 32 + 16 + lm_row) * 528 + lm_kadd;

        uint2 w[4][4];
#pragma unroll
        for (int p = 0; p < 4; p++)
#pragma unroll
            for (int n = 0; n < 4; n++)
                w[p][n] = __ldcg((const uint2*)&g_wf2[((p * 16 + ng * 4 + n) * 32 + lane) * 2]);

#pragma unroll
        for (int kt = 0; kt < 16; kt++) {
            uint32_t ab = sbase + FM_H1 + (uint32_t)kt * 32;
            uint32_t a[2][4];
            ldsm_x4(a[0], ab + ro0);
            ldsm_x4(a[1], ab + ro1);
            uint2 wn[4];
            if (kt < 12) {
#pragma unroll
                for (int n = 0; n < 4; n++)
                    wn[n] = __ldcg((const uint2*)&g_wf2[(((kt + 4) * 16 + ng * 4 + n) * 32 + lane) * 2]);
            }
            const int sl = kt & 3;
#pragma unroll
            for (int n = 0; n < 4; n++) {
                mma_f16(acc[0][n], a[0][0], a[0][1], a[0][2], a[0][3], w[sl][n].x, w[sl][n].y);
                mma_f16(acc[1][n], a[1][0], a[1][1], a[1][2], a[1][3], w[sl][n].x, w[sl][n].y);
            }
            if (kt < 12) {
#pragma unroll
                for (int n = 0; n < 4; n++) w[sl][n] = wn[n];
            }
        }

        __syncthreads();   // all H1 reads done before H2 (aliased) writes
#pragma unroll
        for (int mt = 0; mt < 2; mt++) {
            int rr = mg * 32 + mt * 16 + (lane >> 2);
#pragma unroll
            for (int n = 0; n < 4; n++) {
                int col0 = ng * 32 + n * 8 + (lane & 3) * 2;
                float2 bb = *(const float2*)&sb2[col0];
                float h0 = fmaxf(acc[mt][n][0] + bb.x, 0.f);
                float h1 = fmaxf(acc[mt][n][1] + bb.y, 0.f);
                *(uint32_t*)(sm + FM_H2 + rr * 272 + col0 * 2) = pack_h2(h0, h1);
                float h2 = fmaxf(acc[mt][n][2] + bb.x, 0.f);
                float h3 = fmaxf(acc[mt][n][3] + bb.y, 0.f);
                *(uint32_t*)(sm + FM_H2 + (rr + 8) * 272 + col0 * 2) = pack_h2(h2, h3);
            }
        }
    }
    __syncthreads();

    // ================= layer 3 + head (single fp16): warps 0..3 ===========
    if (wid < 4) {
        const int mg = wid;
        float acc[8][4];
#pragma unroll
        for (int n = 0; n < 8; n++)
#pragma unroll
            for (int j = 0; j < 4; j++) acc[n][j] = 0.f;

        uint32_t ro = (uint32_t)(mg * 16 + lm_row) * 272 + lm_kadd;

        uint2 w[2][8];
#pragma unroll
        for (int p = 0; p < 2; p++)
#pragma unroll
            for (int n = 0; n < 8; n++)
                w[p][n] = __ldcg((const uint2*)&g_wf3[((p * 8 + n) * 32 + lane) * 2]);

#pragma unroll
        for (int kt = 0; kt < 8; kt++) {
            uint32_t ab = sbase + FM_H2 + (uint32_t)kt * 32;
            uint32_t a[4];
            ldsm_x4(a, ab + ro);
            uint2 wn[8];
            if (kt < 6) {
#pragma unroll
                for (int n = 0; n < 8; n++)
                    wn[n] = __ldcg((const uint2*)&g_wf3[(((kt + 2) * 8 + n) * 32 + lane) * 2]);
            }
            const int sl = kt & 1;
#pragma unroll
            for (int n = 0; n < 8; n++)
                mma_f16(acc[n], a[0], a[1], a[2], a[3], w[sl][n].x, w[sl][n].y);
            if (kt < 6) {
#pragma unroll
                for (int n = 0; n < 8; n++) w[sl][n] = wn[n];
            }
        }

        float sum0 = 0.f, sum1 = 0.f;
#pragma unroll
        for (int n = 0; n < 8; n++) {
            int col0 = n * 8 + (lane & 3) * 2;
            float2 bb = *(const float2*)&sb3[col0];
            float2 wv = *(const float2*)&swv[col0];
            sum0 += fmaxf(acc[n][0] + bb.x, 0.f) * wv.x
                  + fmaxf(acc[n][1] + bb.y, 0.f) * wv.y;
            sum1 += fmaxf(acc[n][2] + bb.x, 0.f) * wv.x
                  + fmaxf(acc[n][3] + bb.y, 0.f) * wv.y;
        }
        sum0 += __shfl_xor_sync(0xffffffffu, sum0, 1);
        sum0 += __shfl_xor_sync(0xffffffffu, sum0, 2);
        sum1 += __shfl_xor_sync(0xffffffffu, sum1, 1);
        sum1 += __shfl_xor_sync(0xffffffffu, sum1, 2);
        if ((lane & 3) == 0) {
            int row = r0 + mg * 16 + (lane >> 2);
            float bfv = sbf[0];
            out[row]     = 1.f / (1.f + __expf(-(sum0 + bfv)));
            out[row + 8] = 1.f / (1.f + __expf(-(sum1 + bfv)));
        }
    }
}

// ---------------------------------------------------------------------------
extern "C" void kernel_launch(void* const* d_in, const int* in_sizes, int n_in,
                              void* d_out, int out_size) {
    const float* x_dense = (const float*)d_in[0];
    const void*  x_sparse = d_in[1];
    const float* emb   = (const float*)d_in[2];
    const float* gamma = (const float*)d_in[3];
    const float* beta  = (const float*)d_in[4];
    const float* W1 = (const float*)d_in[5];
    const float* b1 = (const float*)d_in[6];
    const float* W2 = (const float*)d_in[7];
    const float* b2 = (const float*)d_in[8];
    const float* W3 = (const float*)d_in[9];
    const float* b3 = (const float*)d_in[10];
    const float* Wf = (const float*)d_in[11];
    const float* bf = (const float*)d_in[12];
    float* out = (float*)d_out;

    static bool s_attr_done = false;
    if (!s_attr_done) {
        cudaFuncSetAttribute(nfm_kernel,
                             cudaFuncAttributeMaxDynamicSharedMemorySize, FM_SMEM);
        s_attr_done = true;
    }

    nfm_kernel<<<NCTA, 256, FM_SMEM>>>(x_sparse, x_dense, emb,
                                       W1, b1, W2, b2, W3, b3,
                                       Wf, bf, gamma, beta, out);
}

// round 17
// speedup vs baseline: 1.0877x; 1.0877x over previous
#include <cuda_runtime.h>
#include <cuda_fp16.h>
#include <math.h>
#include <stdint.h>

#define B_ROWS 16384
#define NSP 26
#define ND 13
#define VOCAB 100000
#define EMB_D 16
#define F0 29
#define BN_EPS 1e-5f

#define NCTA 296              // 148 SMs x 2 co-resident CTAs
#define NTILE 256             // MLP tiles (64 rows each)

// ---------------------------------------------------------------------------
// Device scratch
// ---------------------------------------------------------------------------
__device__ float g_xbuf[B_ROWS * 32];
__device__ float g_bnpart[NCTA][64];
__device__ unsigned int g_ticket;          // monotonic; +NCTA per launch

// Fragment-ordered fp16x2-packed weights
__device__ uint32_t g_wf1[12288];
__device__ uint32_t g_wf2[16384];
__device__ uint32_t g_wf3[4096];

// ---------------------------------------------------------------------------
__device__ __forceinline__ void mma_f16(float* c, uint32_t a0, uint32_t a1,
                                        uint32_t a2, uint32_t a3,
                                        uint32_t b0, uint32_t b1) {
    asm volatile(
        "mma.sync.aligned.m16n8k16.row.col.f32.f16.f16.f32 "
        "{%0,%1,%2,%3}, {%4,%5,%6,%7}, {%8,%9}, {%0,%1,%2,%3};"
        : "+f"(c[0]), "+f"(c[1]), "+f"(c[2]), "+f"(c[3])
        : "r"(a0), "r"(a1), "r"(a2), "r"(a3), "r"(b0), "r"(b1));
}

__device__ __forceinline__ void ldsm_x4(uint32_t* r, uint32_t addr) {
    asm volatile("ldmatrix.sync.aligned.m8n8.x4.shared.b16 {%0,%1,%2,%3}, [%4];"
                 : "=r"(r[0]), "=r"(r[1]), "=r"(r[2]), "=r"(r[3]) : "r"(addr));
}

__device__ __forceinline__ uint32_t smem_u32(const void* p) {
    uint32_t a;
    asm("{ .reg .u64 t; cvta.to.shared.u64 t, %1; cvt.u32.u64 %0, t; }"
        : "=r"(a) : "l"(p));
    return a;
}

__device__ __forceinline__ uint32_t pack_h2(float a, float b) {
    __half2 h = __floats2half2_rn(a, b);
    return *(uint32_t*)&h;
}

__device__ __forceinline__ void split_pack_h(float h0, float h1,
                                             uint32_t& hi, uint32_t& lo) {
    __half a0 = __float2half_rn(h0);
    __half a1 = __float2half_rn(h1);
    __half c0 = __float2half_rn(h0 - __half2float(a0));
    __half c1 = __float2half_rn(h1 - __half2float(a1));
    hi = ((uint32_t)__half_as_ushort(a1) << 16) | __half_as_ushort(a0);
    lo = ((uint32_t)__half_as_ushort(c1) << 16) | __half_as_ushort(c0);
}

__device__ __forceinline__ unsigned short wpart_f16(float w, bool lo_part) {
    __half h = __float2half_rn(w);
    if (!lo_part) return __half_as_ushort(h);
    return __half_as_ushort(__float2half_rn(w - __half2float(h)));
}

// ---------------------------------------------------------------------------
__device__ __forceinline__ void prep_one(int e, const float* __restrict__ W1,
                                         const float* __restrict__ W2,
                                         const float* __restrict__ W3) {
    if (e < 12288) {
        int r = e & 1, lane = (e >> 1) & 31, nt = (e >> 6) & 31, s = e >> 11;
        bool wlo = (s == 2 || s == 3);
        int kt = s & 1;
        int k = kt * 16 + (lane & 3) * 2 + r * 8;
        int n = nt * 8 + (lane >> 2);
        float w0 = (k < F0)     ? W1[k * 256 + n]       : 0.f;
        float w1 = (k + 1 < F0) ? W1[(k + 1) * 256 + n] : 0.f;
        g_wf1[e] = ((uint32_t)wpart_f16(w1, wlo) << 16) | wpart_f16(w0, wlo);
    } else if (e < 28672) {
        int e2 = e - 12288;
        int r = e2 & 1, lane = (e2 >> 1) & 31, nt = (e2 >> 6) & 15, kt = e2 >> 10;
        int k = kt * 16 + (lane & 3) * 2 + r * 8;
        int n = nt * 8 + (lane >> 2);
        float w0 = W2[k * 128 + n];
        float w1 = W2[(k + 1) * 128 + n];
        g_wf2[e2] = ((uint32_t)wpart_f16(w1, false) << 16) | wpart_f16(w0, false);
    } else {
        int e3 = e - 28672;
        int r = e3 & 1, lane = (e3 >> 1) & 31, nt = (e3 >> 6) & 7, kt = e3 >> 9;
        int k = kt * 16 + (lane & 3) * 2 + r * 8;
        int n = nt * 8 + (lane >> 2);
        float w0 = W3[k * 64 + n];
        float w1 = W3[(k + 1) * 64 + n];
        g_wf3[e3] = ((uint32_t)wpart_f16(w1, false) << 16) | wpart_f16(w0, false);
    }
}

// ---------------------------------------------------------------------------
// SMEM layout (64-row MLP tile). H2 aliases XHI/XLO.
// ---------------------------------------------------------------------------
#define FM_H1    0            // 64*528 = 33792 (fp16)
#define FM_XHI   33792        // 5120
#define FM_XLO   38912        // 5120 -> 44032
#define FM_H2    33792        // 64*272 = 17408 -> 51200 (alias)
#define FM_BIAS  51200        // b1[256] b2[128] b3[64] wf[64] bf[1]
#define FM_SC    53264
#define FM_SH    53392
#define FM_RED   53520        // 4*64 floats
#define FM_SMEM  54544

__global__ void __launch_bounds__(256, 2)
nfm_kernel(const void* __restrict__ xsparse, const float* __restrict__ xdense,
           const float* __restrict__ emb,
           const float* __restrict__ W1, const float* __restrict__ b1,
           const float* __restrict__ W2, const float* __restrict__ b2,
           const float* __restrict__ W3, const float* __restrict__ b3,
           const float* __restrict__ Wf, const float* __restrict__ bf,
           const float* __restrict__ gamma, const float* __restrict__ beta,
           float* __restrict__ out) {
    extern __shared__ char sm[];
    const uint32_t sbase = smem_u32(sm);
    float* sb1 = (float*)(sm + FM_BIAS);
    float* sb2 = sb1 + 256;
    float* sb3 = sb2 + 128;
    float* swv = sb3 + 64;
    float* sbf = swv + 64;
    float* sSC = (float*)(sm + FM_SC);
    float* sSH = (float*)(sm + FM_SH);
    float* sred = (float*)(sm + FM_RED);
    float* swarp = (float*)(sm + FM_H1);   // reuse H1 region during gather

    __shared__ int s_is64;
    __shared__ unsigned s_round;

    const int tid = threadIdx.x;
    const int cta = blockIdx.x;

    // ---- idx-width detect ----
    const int* xs_i32 = (const int*)xsparse;
    if (tid < 32) {
        unsigned m = __ballot_sync(0xffffffffu, xs_i32[2 * tid + 1] != 0);
        if (tid == 0) s_is64 = (m == 0);
    }
    __syncthreads();
    const bool is64 = (s_is64 != 0);

    // ---- balanced gather: CTA c handles rows [c*B/296, (c+1)*B/296) ----
    const long long* xs64 = (const long long*)xsparse;
    const int row_s = (int)(((long long)cta * B_ROWS) / NCTA);
    const int row_e = (int)(((long long)(cta + 1) * B_ROWS) / NCTA);
    const int nquads = (row_e - row_s) * 4;
    const int q = tid & 3;
    const int rg = row_s + (tid >> 2);
    const bool active = (tid < nquads);

    float4 cr = make_float4(0.f, 0.f, 0.f, 0.f);
    float4 dv = make_float4(0.f, 0.f, 0.f, 0.f);
    float q0 = 0.f, q1 = 0.f, q2 = 0.f, q3 = 0.f;

    if (active) {
        int idxs[NSP];
        if (is64) {
#pragma unroll
            for (int f = 0; f < NSP; f++) idxs[f] = (int)xs64[rg * NSP + f];
        } else {
#pragma unroll
            for (int f = 0; f < NSP; f++) idxs[f] = xs_i32[rg * NSP + f];
        }
        float s0 = 0.f, s1 = 0.f, s2 = 0.f, s3 = 0.f;
#pragma unroll
        for (int half = 0; half < 2; half++) {
            float4 v[13];
#pragma unroll
            for (int j = 0; j < 13; j++) {
                int f = half * 13 + j;
                v[j] = *(const float4*)(emb +
                    ((size_t)f * VOCAB + (size_t)idxs[f]) * EMB_D + q * 4);
            }
#pragma unroll
            for (int j = 0; j < 13; j++) {
                s0 += v[j].x; s1 += v[j].y; s2 += v[j].z; s3 += v[j].w;
                q0 += v[j].x * v[j].x; q1 += v[j].y * v[j].y;
                q2 += v[j].z * v[j].z; q3 += v[j].w * v[j].w;
            }
        }
        cr.x = 0.5f * (s0 * s0 - q0);
        cr.y = 0.5f * (s1 * s1 - q1);
        cr.z = 0.5f * (s2 * s2 - q2);
        cr.w = 0.5f * (s3 * s3 - q3);
        int base = q * 4;
        dv.x = (base + 0 < ND) ? xdense[rg * ND + base + 0] : 0.f;
        dv.y = (base + 1 < ND) ? xdense[rg * ND + base + 1] : 0.f;
        dv.z = (base + 2 < ND) ? xdense[rg * ND + base + 2] : 0.f;
        dv.w = (base + 3 < ND) ? xdense[rg * ND + base + 3] : 0.f;
        *(float4*)&g_xbuf[rg * 32 + q * 4] = cr;
        *(float4*)&g_xbuf[rg * 32 + 16 + q * 4] = dv;
    }

    // ---- BN partials (shuffle tree; inactive threads contribute zeros) ----
    {
        float st[16];
        st[0] = cr.x; st[1] = cr.y; st[2] = cr.z; st[3] = cr.w;
        st[4] = cr.x * cr.x; st[5] = cr.y * cr.y; st[6] = cr.z * cr.z; st[7] = cr.w * cr.w;
        st[8] = dv.x; st[9] = dv.y; st[10] = dv.z; st[11] = dv.w;
        st[12] = dv.x * dv.x; st[13] = dv.y * dv.y; st[14] = dv.z * dv.z; st[15] = dv.w * dv.w;
#pragma unroll
        for (int j = 0; j < 16; j++) {
            st[j] += __shfl_xor_sync(0xffffffffu, st[j], 4);
            st[j] += __shfl_xor_sync(0xffffffffu, st[j], 8);
            st[j] += __shfl_xor_sync(0xffffffffu, st[j], 16);
        }
        int wd = tid >> 5, lane = tid & 31;
        if (lane < 4) {
#pragma unroll
            for (int j = 0; j < 16; j++) swarp[(wd * 4 + lane) * 16 + j] = st[j];
        }
        __syncthreads();
        if (tid < 64) {
            int qq = tid >> 4, j = tid & 15;
            float acc = 0.f;
#pragma unroll
            for (int w = 0; w < 8; w++) acc += swarp[(w * 4 + qq) * 16 + j];
            int col, slot;
            if (j < 4)       { col = qq * 4 + j;          slot = col; }
            else if (j < 8)  { col = qq * 4 + (j - 4);    slot = 32 + col; }
            else if (j < 12) { col = 16 + qq * 4 + (j - 8);  slot = col; }
            else             { col = 16 + qq * 4 + (j - 12); slot = 32 + col; }
            g_bnpart[cta][slot] = acc;
        }
    }

    // ---- weight prep (CTAs 0..255 only) ----
    if (cta < NTILE && tid < 128) prep_one(cta * 128 + tid, W1, W2, W3);

    // ---- biases ----
    if (tid < 256) sb1[tid] = b1[tid];
    if (tid < 128) sb2[tid] = b2[tid];
    else if (tid < 192) sb3[tid - 128] = b3[tid - 128];
    else swv[tid - 192] = Wf[tid - 192];
    if (tid == 0) sbf[0] = bf[0];

    // ---- device-wide ticket barrier (all 296 CTAs co-resident) ----
    __threadfence();
    __syncthreads();
    if (tid == 0) {
        unsigned t = atomicAdd(&g_ticket, 1u);
        s_round = t / (unsigned)NCTA;
    }
    __syncthreads();

    if (cta >= NTILE) return;   // gather-only CTAs: arrive and exit

    if (tid == 0) {
        unsigned target = (s_round + 1u) * (unsigned)NCTA;
        unsigned v;
        do {
            asm volatile("ld.acquire.gpu.global.u32 %0, [%1];"
                         : "=r"(v) : "l"(&g_ticket) : "memory");
        } while (v < target);
    }
    __syncthreads();

    const int r0 = cta * 64;
    const int wid = tid >> 5, lane = tid & 31;
    const int lm_m   = lane >> 3;
    const int lm_row = (lane & 7) + ((lm_m & 1) << 3);
    const uint32_t lm_kadd = (uint32_t)(lm_m >> 1) * 16;
    const int mg1 = wid & 1, ng1 = wid >> 1;

    // layer-1 s=0 weight prefetch (covers BN finalize + X staging)
    uint2 w1buf[8];
#pragma unroll
    for (int n = 0; n < 8; n++)
        w1buf[n] = __ldcg((const uint2*)&g_wf1[((ng1 * 8 + n) * 32 + lane) * 2]);

    // ---- BN finalize (per-CTA redundant, parallel; fixed order) ----
    {
        int slot = tid & 63, seg = tid >> 6;    // 4 segs x 74 blocks
        float acc = 0.f;
        for (int b = seg * 74; b < seg * 74 + 74; b++)
            acc += __ldcg(&g_bnpart[b][slot]);
        sred[seg * 64 + slot] = acc;
    }
    __syncthreads();
    if (tid < 32) {
        float s = 0.f, s2 = 0.f;
#pragma unroll
        for (int c = 0; c < 4; c++) { s += sred[c * 64 + tid]; s2 += sred[c * 64 + 32 + tid]; }
        float mean = s * (1.0f / B_ROWS);
        float var  = s2 * (1.0f / B_ROWS) - mean * mean;
        if (tid < F0) {
            float sc = gamma[tid] * rsqrtf(var + BN_EPS);
            sSC[tid] = sc;
            sSH[tid] = beta[tid] - mean * sc;
        } else { sSC[tid] = 0.f; sSH[tid] = 0.f; }
    }
    __syncthreads();

    // ---- stage X: read gathered rows, BN + fp16 split ----
    {
        int rloc = tid >> 2, qq = tid & 3;
        float4 v0 = __ldcg((const float4*)&g_xbuf[(r0 + rloc) * 32 + qq * 8]);
        float4 v1 = __ldcg((const float4*)&g_xbuf[(r0 + rloc) * 32 + qq * 8 + 4]);
        float4 sc0 = *(const float4*)&sSC[qq * 8];
        float4 sc1 = *(const float4*)&sSC[qq * 8 + 4];
        float4 sh0 = *(const float4*)&sSH[qq * 8];
        float4 sh1 = *(const float4*)&sSH[qq * 8 + 4];
        float x0 = v0.x * sc0.x + sh0.x, x1 = v0.y * sc0.y + sh0.y;
        float x2 = v0.z * sc0.z + sh0.z, x3 = v0.w * sc0.w + sh0.w;
        float x4 = v1.x * sc1.x + sh1.x, x5 = v1.y * sc1.y + sh1.y;
        float x6 = v1.z * sc1.z + sh1.z, x7 = v1.w * sc1.w + sh1.w;
        uint4 uh, ul;
        split_pack_h(x0, x1, uh.x, ul.x);
        split_pack_h(x2, x3, uh.y, ul.y);
        split_pack_h(x4, x5, uh.z, ul.z);
        split_pack_h(x6, x7, uh.w, ul.w);
        *(uint4*)(sm + FM_XHI + rloc * 80 + qq * 16) = uh;
        *(uint4*)(sm + FM_XLO + rloc * 80 + qq * 16) = ul;
    }
    __syncthreads();

    // ================= layer 1 (3-term fp16): [64x32] x [32x256] =========
    {
        float acc[2][8][4];
#pragma unroll
        for (int m = 0; m < 2; m++)
#pragma unroll
            for (int n = 0; n < 8; n++)
#pragma unroll
                for (int j = 0; j < 4; j++) acc[m][n][j] = 0.f;

        uint32_t ro0 = (uint32_t)(mg1 * 32 + lm_row) * 80 + lm_kadd;
        uint32_t ro1 = (uint32_t)(mg1 * 32 + 16 + lm_row) * 80 + lm_kadd;

#pragma unroll
        for (int s = 0; s < 6; s++) {
            uint32_t ab = sbase + ((s >= 4) ? FM_XLO : FM_XHI) + (uint32_t)(s & 1) * 32;
            uint32_t a[2][4];
            ldsm_x4(a[0], ab + ro0);
            ldsm_x4(a[1], ab + ro1);
            uint2 wn[8];
            if (s < 5) {
#pragma unroll
                for (int n = 0; n < 8; n++)
                    wn[n] = __ldcg((const uint2*)&g_wf1[(((s + 1) * 32 + ng1 * 8 + n) * 32 + lane) * 2]);
            }
#pragma unroll
            for (int n = 0; n < 8; n++) {
                mma_f16(acc[0][n], a[0][0], a[0][1], a[0][2], a[0][3], w1buf[n].x, w1buf[n].y);
                mma_f16(acc[1][n], a[1][0], a[1][1], a[1][2], a[1][3], w1buf[n].x, w1buf[n].y);
            }
            if (s < 5) {
#pragma unroll
                for (int n = 0; n < 8; n++) w1buf[n] = wn[n];
            }
        }

#pragma unroll
        for (int mt = 0; mt < 2; mt++) {
            int rr = mg1 * 32 + mt * 16 + (lane >> 2);
#pragma unroll
            for (int n = 0; n < 8; n++) {
                int c0 = ng1 * 64 + n * 8 + (lane & 3) * 2;
                float2 bb = *(const float2*)&sb1[c0];
                float h0 = fmaxf(acc[mt][n][0] + bb.x, 0.f);
                float h1 = fmaxf(acc[mt][n][1] + bb.y, 0.f);
                *(uint32_t*)(sm + FM_H1 + rr * 528 + c0 * 2) = pack_h2(h0, h1);
                float h2 = fmaxf(acc[mt][n][2] + bb.x, 0.f);
                float h3 = fmaxf(acc[mt][n][3] + bb.y, 0.f);
                *(uint32_t*)(sm + FM_H1 + (rr + 8) * 528 + c0 * 2) = pack_h2(h2, h3);
            }
        }
    }
    __syncthreads();

    // ================= layer 2 (single fp16): [64x256] x [256x128] ========
    {
        const int mg = wid & 1, ng = wid >> 1;
        float acc[2][4][4];
#pragma unroll
        for (int m = 0; m < 2; m++)
#pragma unroll
            for (int n = 0; n < 4; n++)
#pragma unroll
                for (int j = 0; j < 4; j++) acc[m][n][j] = 0.f;

        uint32_t ro0 = (uint32_t)(mg * 32 + lm_row) * 528 + lm_kadd;
        uint32_t ro1 = (uint32_t)(mg * 32 + 16 + lm_row) * 528 + lm_kadd;

        uint2 w[4][4];
#pragma unroll
        for (int p = 0; p < 4; p++)
#pragma unroll
            for (int n = 0; n < 4; n++)
                w[p][n] = __ldcg((const uint2*)&g_wf2[((p * 16 + ng * 4 + n) * 32 + lane) * 2]);

#pragma unroll
        for (int kt = 0; kt < 16; kt++) {
            uint32_t ab = sbase + FM_H1 + (uint32_t)kt * 32;
            uint32_t a[2][4];
            ldsm_x4(a[0], ab + ro0);
            ldsm_x4(a[1], ab + ro1);
            uint2 wn[4];
            if (kt < 12) {
#pragma unroll
                for (int n = 0; n < 4; n++)
                    wn[n] = __ldcg((const uint2*)&g_wf2[(((kt + 4) * 16 + ng * 4 + n) * 32 + lane) * 2]);
            }
            const int sl = kt & 3;
#pragma unroll
            for (int n = 0; n < 4; n++) {
                mma_f16(acc[0][n], a[0][0], a[0][1], a[0][2], a[0][3], w[sl][n].x, w[sl][n].y);
                mma_f16(acc[1][n], a[1][0], a[1][1], a[1][2], a[1][3], w[sl][n].x, w[sl][n].y);
            }
            if (kt < 12) {
#pragma unroll
                for (int n = 0; n < 4; n++) w[sl][n] = wn[n];
            }
        }

        __syncthreads();   // all H1 reads done before H2 (aliased) writes
#pragma unroll
        for (int mt = 0; mt < 2; mt++) {
            int rr = mg * 32 + mt * 16 + (lane >> 2);
#pragma unroll
            for (int n = 0; n < 4; n++) {
                int col0 = ng * 32 + n * 8 + (lane & 3) * 2;
                float2 bb = *(const float2*)&sb2[col0];
                float h0 = fmaxf(acc[mt][n][0] + bb.x, 0.f);
                float h1 = fmaxf(acc[mt][n][1] + bb.y, 0.f);
                *(uint32_t*)(sm + FM_H2 + rr * 272 + col0 * 2) = pack_h2(h0, h1);
                float h2 = fmaxf(acc[mt][n][2] + bb.x, 0.f);
                float h3 = fmaxf(acc[mt][n][3] + bb.y, 0.f);
                *(uint32_t*)(sm + FM_H2 + (rr + 8) * 272 + col0 * 2) = pack_h2(h2, h3);
            }
        }
    }
    __syncthreads();

    // ================= layer 3 + head (single fp16): warps 0..3 ===========
    if (wid < 4) {
        const int mg = wid;
        float acc[8][4];
#pragma unroll
        for (int n = 0; n < 8; n++)
#pragma unroll
            for (int j = 0; j < 4; j++) acc[n][j] = 0.f;

        uint32_t ro = (uint32_t)(mg * 16 + lm_row) * 272 + lm_kadd;

        uint2 w[2][8];
#pragma unroll
        for (int p = 0; p < 2; p++)
#pragma unroll
            for (int n = 0; n < 8; n++)
                w[p][n] = __ldcg((const uint2*)&g_wf3[((p * 8 + n) * 32 + lane) * 2]);

#pragma unroll
        for (int kt = 0; kt < 8; kt++) {
            uint32_t ab = sbase + FM_H2 + (uint32_t)kt * 32;
            uint32_t a[4];
            ldsm_x4(a, ab + ro);
            uint2 wn[8];
            if (kt < 6) {
#pragma unroll
                for (int n = 0; n < 8; n++)
                    wn[n] = __ldcg((const uint2*)&g_wf3[(((kt + 2) * 8 + n) * 32 + lane) * 2]);
            }
            const int sl = kt & 1;
#pragma unroll
            for (int n = 0; n < 8; n++)
                mma_f16(acc[n], a[0], a[1], a[2], a[3], w[sl][n].x, w[sl][n].y);
            if (kt < 6) {
#pragma unroll
                for (int n = 0; n < 8; n++) w[sl][n] = wn[n];
            }
        }

        float sum0 = 0.f, sum1 = 0.f;
#pragma unroll
        for (int n = 0; n < 8; n++) {
            int col0 = n * 8 + (lane & 3) * 2;
            float2 bb = *(const float2*)&sb3[col0];
            float2 wv = *(const float2*)&swv[col0];
            sum0 += fmaxf(acc[n][0] + bb.x, 0.f) * wv.x
                  + fmaxf(acc[n][1] + bb.y, 0.f) * wv.y;
            sum1 += fmaxf(acc[n][2] + bb.x, 0.f) * wv.x
                  + fmaxf(acc[n][3] + bb.y, 0.f) * wv.y;
        }
        sum0 += __shfl_xor_sync(0xffffffffu, sum0, 1);
        sum0 += __shfl_xor_sync(0xffffffffu, sum0, 2);
        sum1 += __shfl_xor_sync(0xffffffffu, sum1, 1);
        sum1 += __shfl_xor_sync(0xffffffffu, sum1, 2);
        if ((lane & 3) == 0) {
            int row = r0 + mg * 16 + (lane >> 2);
            float bfv = sbf[0];
            out[row]     = 1.f / (1.f + __expf(-(sum0 + bfv)));
            out[row + 8] = 1.f / (1.f + __expf(-(sum1 + bfv)));
        }
    }
}

// ---------------------------------------------------------------------------
extern "C" void kernel_launch(void* const* d_in, const int* in_sizes, int n_in,
                              void* d_out, int out_size) {
    const float* x_dense = (const float*)d_in[0];
    const void*  x_sparse = d_in[1];
    const float* emb   = (const float*)d_in[2];
    const float* gamma = (const float*)d_in[3];
    const float* beta  = (const float*)d_in[4];
    const float* W1 = (const float*)d_in[5];
    const float* b1 = (const float*)d_in[6];
    const float* W2 = (const float*)d_in[7];
    const float* b2 = (const float*)d_in[8];
    const float* W3 = (const float*)d_in[9];
    const float* b3 = (const float*)d_in[10];
    const float* Wf = (const float*)d_in[11];
    const float* bf = (const float*)d_in[12];
    float* out = (float*)d_out;

    static bool s_attr_done = false;
    if (!s_attr_done) {
        cudaFuncSetAttribute(nfm_kernel,
                             cudaFuncAttributeMaxDynamicSharedMemorySize, FM_SMEM);
        s_attr_done = true;
    }

    nfm_kernel<<<NCTA, 256, FM_SMEM>>>(x_sparse, x_dense, emb,
                                       W1, b1, W2, b2, W3, b3,
                                       Wf, bf, gamma, beta, out);
}